// round 6
// baseline (speedup 1.0000x reference)
#include <cuda_runtime.h>

#define T_STEPS 1024
#define WIN 64                       // live window: weights < 1e-12 earlier
#define WIN_PAIRS (WIN / 2)          // 32
#define T_HEAD (T_STEPS - WIN)       // 960
#define NBLK 128
#define NTHR 512
#define FULLM 0xffffffffu

// Single fused kernel. 128 blocks x 512 threads; warp handles 2 sequences.
// z prefetch at kernel top hides DRAM under the per-block redundant Riccati.
// The Riccati runs LANE-PARALLEL on warp 0: lane (i*4+j) owns P(i,j), one
// iteration = 3 shuffle layers + ~25 ALU ops (~120 cyc chain) instead of a
// ~400-cycle single-thread RAW chain. Then 16-lane shuffle squarings,
// W_n = Ainf^n Kinf by 64 threads, weighted sum + warp reduce + store.
__global__ void __launch_bounds__(NTHR) kf_fused(const float* __restrict__ hist,
                                                 const float* __restrict__ Qlog,
                                                 const float* __restrict__ Rlog,
                                                 float* __restrict__ out) {
    __shared__ float sW[WIN_PAIRS * 17];   // pair layout + pad
    __shared__ float sQR[20];              // exp(Qlog) (16) + exp(Rlog) (4)
    __shared__ float sApow[6][16];         // Ainf^(2^k)
    __shared__ float sKinf[8];
    __shared__ int   s_mode;               // 0 = converged, 1 = exact fallback
    __shared__ float sAwin[WIN * 16];      // fallback scratch
    __shared__ float sKwin[WIN * 8];

    int tid = threadIdx.x, warp = tid >> 5, lane = tid & 31;
    int bA = (blockIdx.x * 16 + warp) * 2;
    int bB = bA + 1;
    const float4* rowA = reinterpret_cast<const float4*>(hist) + (size_t)bA * 512;
    const float4* rowB = reinterpret_cast<const float4*>(hist) + (size_t)bB * 512;

    // Prefetch window pairs [480, 512) — in flight during the Riccati.
    float4 zA = rowA[480 + lane];
    float4 zB = rowB[480 + lane];

    if (warp == 0) {
        // Parallel prologue: 20 lanes do loads + expf concurrently.
        if (lane < 20) {
            float v = (lane < 16) ? expf(Qlog[lane]) : expf(Rlog[lane - 16]);
            if (lane == 0 || lane == 5 || lane == 10 || lane == 15 ||
                lane == 16 || lane == 19)
                v += 1e-6f;
            sQR[lane] = v;
        }
        __syncwarp();

        // Lane-parallel Riccati. Lanes 16-31 mirror 0-15 (same inputs, same
        // results) so full-mask shuffles stay valid and branches stay uniform.
        int l16 = lane & 15;
        int li = l16 >> 2, lj = l16 & 3;
        float mi  = (li < 2) ? 1.f : 0.f;
        float mj  = (lj < 2) ? 1.f : 0.f;
        float mij = mi * mj;
        int src1 = (((li + 2) & 3) << 2) | lj;              // P(i+2, j)
        int src2 = (li << 2) | ((lj + 2) & 3);              // P(i, j+2)
        int src3 = (((li + 2) & 3) << 2) | ((lj + 2) & 3);  // P(i+2, j+2)

        float q  = sQR[l16];
        float R0 = sQR[16], R1 = sQR[17], R2 = sQR[18], R3 = sQR[19];

        float p = (li == lj) ? 1000.f : 0.f;   // P0 = 1000*I
        float kn0 = 0.f, kn1 = 0.f;            // NEGATED gain, row li
        float k0p = 1e30f, k1p = 1e30f;
        int mode = 1, stable = 0;

        for (int t = 0; t < T_HEAD; t++) {
            // Pp = F P F^T + Q (elementwise with masked neighbor shuffles)
            float t1 = __shfl_sync(FULLM, p, src1);
            float t2 = __shfl_sync(FULLM, p, src2);
            float t3 = __shfl_sync(FULLM, p, src3);
            float pp = fmaf(mi, t1, p);
            pp = fmaf(mj, t2, pp);
            pp = fmaf(mij, t3, pp);
            pp += q;
            // S = Pp[0:2,0:2] + R; negated 2x2 inverse, redundant on all lanes
            float pp00 = __shfl_sync(FULLM, pp, 0);
            float pp01 = __shfl_sync(FULLM, pp, 1);
            float pp10 = __shfl_sync(FULLM, pp, 4);
            float pp11 = __shfl_sync(FULLM, pp, 5);
            float s00 = pp00 + R0, s01 = pp01 + R1;
            float s10 = pp10 + R2, s11 = pp11 + R3;
            float id = __fdividef(1.0f, fmaf(s00, s11, -s01 * s10));
            float j00 = -s11 * id, j01 = s01 * id;
            float j10 =  s10 * id, j11 = -s00 * id;
            // Row/column gathers for gain + update
            float ppi0 = __shfl_sync(FULLM, pp, li << 2);
            float ppi1 = __shfl_sync(FULLM, pp, (li << 2) | 1);
            float pp0j = __shfl_sync(FULLM, pp, lj);
            float pp1j = __shfl_sync(FULLM, pp, 4 | lj);
            kn0 = fmaf(ppi0, j00, ppi1 * j10);   // -K(li,0)
            kn1 = fmaf(ppi0, j01, ppi1 * j11);   // -K(li,1)
            // P = Pp + kn0*Pp[0,:] + kn1*Pp[1,:]  (== (I-KH)Pp)
            p = fmaf(kn0, pp0j, fmaf(kn1, pp1j, pp));
            // Convergence: all 8 gain entries, per-row relative + tiny floor
            if (t >= 12) {
                float d  = fmaxf(fabsf(kn0 - k0p), fabsf(kn1 - k1p));
                float km = fmaxf(fabsf(kn0), fabsf(kn1));
                bool ok = (d <= fmaf(1e-5f, km, 1e-9f));
                if (__all_sync(FULLM, ok)) {
                    if (++stable >= 3) { mode = 0; break; }
                } else {
                    stable = 0;
                }
            }
            k0p = kn0; k1p = kn1;
        }

        // A(li,lj) from the row gain: a0 = d_{i0}+kn0, a1 = d_{i1}+kn1,
        // cols: [a0, a1, a0+d_{i2}, a1+d_{i3}]
        auto lane_A = [&](float k0, float k1) {
            float base = (lj & 1) ? k1 : k0;
            float d1 = (((lj & 1) ? (li == 1) : (li == 0))) ? 1.f : 0.f;
            float d2 = (lj >= 2 && li == lj) ? 1.f : 0.f;
            return base + d1 + d2;
        };

        if (mode == 0) {
            float a = lane_A(kn0, kn1);
            if (lane < 16) sApow[0][lane] = a;
            if (lj == 0 && lane < 16) {
                sKinf[li * 2 + 0] = -kn0;
                sKinf[li * 2 + 1] = -kn1;
            }
            // Shuffle squarings: lane (i*4+j) owns element (i,j)
#pragma unroll
            for (int k = 1; k < 6; k++) {
                float c = 0.0f;
#pragma unroll
                for (int m = 0; m < 4; m++) {
                    float rim = __shfl_sync(FULLM, a, li * 4 + m);
                    float rmj = __shfl_sync(FULLM, a, m * 4 + lj);
                    c = fmaf(rim, rmj, c);
                }
                a = c;
                if (lane < 16) sApow[k][lane] = a;
            }
        } else {
            // No early convergence: WIN more exact lane-parallel steps,
            // recording A_t and K_t for the backward suffix.
            for (int tw = 0; tw < WIN; tw++) {
                float t1 = __shfl_sync(FULLM, p, src1);
                float t2 = __shfl_sync(FULLM, p, src2);
                float t3 = __shfl_sync(FULLM, p, src3);
                float pp = fmaf(mi, t1, p);
                pp = fmaf(mj, t2, pp);
                pp = fmaf(mij, t3, pp);
                pp += q;
                float pp00 = __shfl_sync(FULLM, pp, 0);
                float pp01 = __shfl_sync(FULLM, pp, 1);
                float pp10 = __shfl_sync(FULLM, pp, 4);
                float pp11 = __shfl_sync(FULLM, pp, 5);
                float s00 = pp00 + R0, s01 = pp01 + R1;
                float s10 = pp10 + R2, s11 = pp11 + R3;
                float id = __fdividef(1.0f, fmaf(s00, s11, -s01 * s10));
                float j00 = -s11 * id, j01 = s01 * id;
                float j10 =  s10 * id, j11 = -s00 * id;
                float ppi0 = __shfl_sync(FULLM, pp, li << 2);
                float ppi1 = __shfl_sync(FULLM, pp, (li << 2) | 1);
                float pp0j = __shfl_sync(FULLM, pp, lj);
                float pp1j = __shfl_sync(FULLM, pp, 4 | lj);
                kn0 = fmaf(ppi0, j00, ppi1 * j10);
                kn1 = fmaf(ppi0, j01, ppi1 * j11);
                p = fmaf(kn0, pp0j, fmaf(kn1, pp1j, pp));
                if (lane < 16) {
                    sAwin[tw * 16 + lane] = lane_A(kn0, kn1);
                    if (lj == 0) {
                        sKwin[tw * 8 + li * 2 + 0] = -kn0;
                        sKwin[tw * 8 + li * 2 + 1] = -kn1;
                    }
                }
            }
            __syncwarp();
            if (lane == 0) {
                // Exact backward suffix within the window (pre-window terms
                // decayed through 960 contraction steps).
                float S[16];
#pragma unroll
                for (int s = 0; s < 16; s++) S[s] = (s % 5 == 0) ? 1.0f : 0.0f;
                for (int tw = WIN - 1; tw >= 0; tw--) {
                    const float* K = &sKwin[tw * 8];
                    float V[8];
#pragma unroll
                    for (int i = 0; i < 4; i++) {
#pragma unroll
                        for (int c = 0; c < 2; c++) {
                            float s = S[i * 4 + 0] * K[0 * 2 + c];
                            s = fmaf(S[i * 4 + 1], K[1 * 2 + c], s);
                            s = fmaf(S[i * 4 + 2], K[2 * 2 + c], s);
                            s = fmaf(S[i * 4 + 3], K[3 * 2 + c], s);
                            V[i * 2 + c] = s;
                        }
                    }
                    int pw = tw >> 1, sub = tw & 1;   // (T_HEAD+tw)&1 == tw&1
#pragma unroll
                    for (int s = 0; s < 8; s++) sW[pw * 17 + sub * 8 + s] = V[s];
                    const float* Aw = &sAwin[tw * 16];
                    float Sn[16];
#pragma unroll
                    for (int i = 0; i < 4; i++) {
#pragma unroll
                        for (int c = 0; c < 4; c++) {
                            float s = S[i * 4 + 0] * Aw[0 * 4 + c];
                            s = fmaf(S[i * 4 + 1], Aw[1 * 4 + c], s);
                            s = fmaf(S[i * 4 + 2], Aw[2 * 4 + c], s);
                            s = fmaf(S[i * 4 + 3], Aw[3 * 4 + c], s);
                            Sn[i * 4 + c] = s;
                        }
                    }
#pragma unroll
                    for (int s = 0; s < 16; s++) S[s] = Sn[s];
                }
            }
        }
        if (lane == 0) s_mode = mode;
    }
    __syncthreads();

    // Fast path: thread n builds W_{T-1-n} = Ainf^n Kinf (n = 0..63).
    if (s_mode == 0 && tid < WIN) {
        int n = tid;
        float V[8];
#pragma unroll
        for (int q = 0; q < 8; q++) V[q] = sKinf[q];
#pragma unroll
        for (int k = 0; k < 6; k++) {
            if ((n >> k) & 1) {
                const float* M = sApow[k];
                float Vn[8];
#pragma unroll
                for (int i = 0; i < 4; i++) {
#pragma unroll
                    for (int c = 0; c < 2; c++) {
                        float s = M[i * 4 + 0] * V[0 * 2 + c];
                        s = fmaf(M[i * 4 + 1], V[1 * 2 + c], s);
                        s = fmaf(M[i * 4 + 2], V[2 * 2 + c], s);
                        s = fmaf(M[i * 4 + 3], V[3 * 2 + c], s);
                        Vn[i * 2 + c] = s;
                    }
                }
#pragma unroll
                for (int q = 0; q < 8; q++) V[q] = Vn[q];
            }
        }
        int tw = WIN - 1 - n;
        int pw = tw >> 1, sub = tw & 1;
#pragma unroll
        for (int q = 0; q < 8; q++) sW[pw * 17 + sub * 8 + q] = V[q];
    }
    __syncthreads();

    // Weighted sum: lane handles pair (T_HEAD + 2*lane, +1) for 2 sequences.
    float a0 = 0.f, a1 = 0.f, a2 = 0.f, a3 = 0.f;
    float c0 = 0.f, c1 = 0.f, c2 = 0.f, c3 = 0.f;
    const float* w = &sW[lane * 17];

    a0 = fmaf(w[0],  zA.x, a0); a0 = fmaf(w[1],  zA.y, a0);
    a1 = fmaf(w[2],  zA.x, a1); a1 = fmaf(w[3],  zA.y, a1);
    a2 = fmaf(w[4],  zA.x, a2); a2 = fmaf(w[5],  zA.y, a2);
    a3 = fmaf(w[6],  zA.x, a3); a3 = fmaf(w[7],  zA.y, a3);
    a0 = fmaf(w[8],  zA.z, a0); a0 = fmaf(w[9],  zA.w, a0);
    a1 = fmaf(w[10], zA.z, a1); a1 = fmaf(w[11], zA.w, a1);
    a2 = fmaf(w[12], zA.z, a2); a2 = fmaf(w[13], zA.w, a2);
    a3 = fmaf(w[14], zA.z, a3); a3 = fmaf(w[15], zA.w, a3);

    c0 = fmaf(w[0],  zB.x, c0); c0 = fmaf(w[1],  zB.y, c0);
    c1 = fmaf(w[2],  zB.x, c1); c1 = fmaf(w[3],  zB.y, c1);
    c2 = fmaf(w[4],  zB.x, c2); c2 = fmaf(w[5],  zB.y, c2);
    c3 = fmaf(w[6],  zB.x, c3); c3 = fmaf(w[7],  zB.y, c3);
    c0 = fmaf(w[8],  zB.z, c0); c0 = fmaf(w[9],  zB.w, c0);
    c1 = fmaf(w[10], zB.z, c1); c1 = fmaf(w[11], zB.w, c1);
    c2 = fmaf(w[12], zB.z, c2); c2 = fmaf(w[13], zB.w, c2);
    c3 = fmaf(w[14], zB.z, c3); c3 = fmaf(w[15], zB.w, c3);

#pragma unroll
    for (int s = 16; s > 0; s >>= 1) {
        a0 += __shfl_xor_sync(FULLM, a0, s);
        a1 += __shfl_xor_sync(FULLM, a1, s);
        a2 += __shfl_xor_sync(FULLM, a2, s);
        a3 += __shfl_xor_sync(FULLM, a3, s);
        c0 += __shfl_xor_sync(FULLM, c0, s);
        c1 += __shfl_xor_sync(FULLM, c1, s);
        c2 += __shfl_xor_sync(FULLM, c2, s);
        c3 += __shfl_xor_sync(FULLM, c3, s);
    }

    if (lane == 0) {
        float* oA = out + (size_t)bA * 6;
        oA[0] = a0 + a2;            oA[1] = a1 + a3;
        oA[2] = fmaf(2.f, a2, a0);  oA[3] = fmaf(2.f, a3, a1);
        oA[4] = fmaf(3.f, a2, a0);  oA[5] = fmaf(3.f, a3, a1);
        float* oB = out + (size_t)bB * 6;
        oB[0] = c0 + c2;            oB[1] = c1 + c3;
        oB[2] = fmaf(2.f, c2, c0);  oB[3] = fmaf(2.f, c3, c1);
        oB[4] = fmaf(3.f, c2, c0);  oB[5] = fmaf(3.f, c3, c1);
    }
}

extern "C" void kernel_launch(void* const* d_in, const int* in_sizes, int n_in,
                              void* d_out, int out_size) {
    const float* hist = (const float*)d_in[0];
    const float* Qlog = (const float*)d_in[1];
    const float* Rlog = (const float*)d_in[2];
    float* out = (float*)d_out;

    kf_fused<<<NBLK, NTHR>>>(hist, Qlog, Rlog, out);
}